// round 2
// baseline (speedup 1.0000x reference)
#include <cuda_runtime.h>
#include <cuda_bf16.h>
#include <cstdint>

// ============================================================================
// Problem dims
// ============================================================================
#define D_DIM   4096
#define M_ROWS  32768            // 8 * 4096

// GEMM tiling (legacy mma.sync int8 path — tcgen05 not available at .target sm_103)
#define TILE_M   128
#define TILE_N   128
#define TILE_K   64              // int8 elems per K-chunk (64 bytes/row in smem)
#define KCHUNKS  (D_DIM / TILE_K)   // 64
#define NSTAGE   3

// SMEM per stage: A 128x64B = 8KB, B 128x64B = 8KB
#define STAGE_SZ   16384
#define A_OFF      0
#define B_OFF      8192
#define SMEM_BYTES (NSTAGE * STAGE_SZ)   // 49152

// ============================================================================
// Scratch (device globals; no allocation anywhere)
// ============================================================================
__device__ __align__(256) int8_t g_q[(size_t)M_ROWS * D_DIM];   // 128 MB
__device__ __align__(256) int8_t g_w[(size_t)D_DIM * D_DIM];    // 16 MB, [f][d] = sign
__device__ float  g_rs[M_ROWS];   // 1 / x_scale^2 per row
__device__ double g_ksum;

// ============================================================================
// Helpers
// ============================================================================
__device__ __forceinline__ uint32_t smem_to_u32(const void* smem_ptr) {
    uint32_t addr;
    asm("{ .reg .u64 tmp; cvta.to.shared.u64 tmp, %1; cvt.u32.u64 %0, tmp; }"
        : "=r"(addr) : "l"(smem_ptr));
    return addr;
}

// 16B-granule swizzle: logical (row, k16chunk) -> byte offset within a tile.
// chunk' = k16 ^ ((row>>1)&3): conflict-free for ldmatrix (8 rows/phase) and STS.
__device__ __forceinline__ uint32_t sw_off(int row, int k16) {
    return (uint32_t)(row * 64 + ((k16 ^ ((row >> 1) & 3)) << 4));
}

__device__ __forceinline__ void cp_async16(uint32_t smem_addr, const void* gptr) {
    asm volatile("cp.async.cg.shared.global [%0], [%1], 16;"
                 :: "r"(smem_addr), "l"(__cvta_generic_to_global(gptr)) : "memory");
}
__device__ __forceinline__ void cp_commit() {
    asm volatile("cp.async.commit_group;" ::: "memory");
}
template <int N>
__device__ __forceinline__ void cp_wait() {
    asm volatile("cp.async.wait_group %0;" :: "n"(N) : "memory");
}

__device__ __forceinline__ void ldm_x4(uint32_t* r, uint32_t addr) {
    asm volatile("ldmatrix.sync.aligned.m8n8.x4.shared.b16 {%0,%1,%2,%3}, [%4];"
                 : "=r"(r[0]), "=r"(r[1]), "=r"(r[2]), "=r"(r[3]) : "r"(addr));
}

__device__ __forceinline__ void mma_s8(int* c, const uint32_t* a, uint32_t b0, uint32_t b1) {
    asm volatile(
        "mma.sync.aligned.m16n8k32.row.col.s32.s8.s8.s32 "
        "{%0,%1,%2,%3}, {%4,%5,%6,%7}, {%8,%9}, {%0,%1,%2,%3};"
        : "+r"(c[0]), "+r"(c[1]), "+r"(c[2]), "+r"(c[3])
        : "r"(a[0]), "r"(a[1]), "r"(a[2]), "r"(a[3]), "r"(b0), "r"(b1));
}

// ============================================================================
// Kernel 0/1: kernel-matrix mean (double accumulate)
// ============================================================================
__global__ void zero_kernel() { g_ksum = 0.0; }

__global__ void ksum_kernel(const float* __restrict__ k) {
    float s = 0.f;
    const float4* k4 = (const float4*)k;
    const int n4 = (D_DIM * D_DIM) / 4;
    for (int i = blockIdx.x * blockDim.x + threadIdx.x; i < n4; i += gridDim.x * blockDim.x) {
        float4 v = k4[i];
        s += v.x + v.y + v.z + v.w;
    }
#pragma unroll
    for (int o = 16; o > 0; o >>= 1) s += __shfl_xor_sync(0xffffffffu, s, o);
    __shared__ float sb[8];
    int wid = threadIdx.x >> 5, lid = threadIdx.x & 31;
    if (lid == 0) sb[wid] = s;
    __syncthreads();
    if (threadIdx.x == 0) {
        float t = 0.f;
        for (int i = 0; i < 8; i++) t += sb[i];
        atomicAdd(&g_ksum, (double)t);
    }
}

// ============================================================================
// Kernel 2: sign(kernel - mean), transposed to [f][d] as int8 {-1,0,+1}
// ============================================================================
__global__ void sign_kernel(const float* __restrict__ k) {
    __shared__ float t[32][33];
    float mean = (float)(g_ksum * (1.0 / 16777216.0));
    int d = blockIdx.y * 32 + threadIdx.y;
    int f = blockIdx.x * 32 + threadIdx.x;
    t[threadIdx.y][threadIdx.x] = k[(size_t)d * D_DIM + f];
    __syncthreads();
    int f2 = blockIdx.x * 32 + threadIdx.y;
    int d2 = blockIdx.y * 32 + threadIdx.x;
    float v = t[threadIdx.x][threadIdx.y] - mean;
    int8_t s = (v > 0.f) ? 1 : ((v < 0.f) ? -1 : 0);
    g_w[(size_t)f2 * D_DIM + d2] = s;
}

// ============================================================================
// Kernel 3: per-row RMSNorm + int8 quant -> g_q (int8), and 1/x_scale^2
// ============================================================================
__global__ void quant_kernel(const float* __restrict__ x) {
    int row = blockIdx.x;
    int tid = threadIdx.x;
    const float4* xr = (const float4*)(x + (size_t)row * D_DIM);
    float4 v[4];
    float ss = 0.f, am = 0.f;
#pragma unroll
    for (int i = 0; i < 4; i++) {
        v[i] = xr[tid + i * 256];
        ss += v[i].x * v[i].x + v[i].y * v[i].y + v[i].z * v[i].z + v[i].w * v[i].w;
        am = fmaxf(am, fmaxf(fmaxf(fabsf(v[i].x), fabsf(v[i].y)),
                             fmaxf(fabsf(v[i].z), fabsf(v[i].w))));
    }
#pragma unroll
    for (int o = 16; o > 0; o >>= 1) {
        ss += __shfl_xor_sync(0xffffffffu, ss, o);
        am = fmaxf(am, __shfl_xor_sync(0xffffffffu, am, o));
    }
    __shared__ float s_ss[8], s_am[8];
    __shared__ float sh_rinv, sh_sc;
    int wid = tid >> 5, lid = tid & 31;
    if (lid == 0) { s_ss[wid] = ss; s_am[wid] = am; }
    __syncthreads();
    if (tid == 0) {
        float t = 0.f, m = 0.f;
        for (int i = 0; i < 8; i++) { t += s_ss[i]; m = fmaxf(m, s_am[i]); }
        float rinv = rsqrtf(t * (1.f / 4096.f) + 1e-5f);
        float amax = m * rinv;                       // == max|x_norm| (monotone)
        float sc = 127.f / fmaxf(amax, 1e-5f);
        sh_rinv = rinv; sh_sc = sc;
        g_rs[row] = 1.f / (sc * sc);
    }
    __syncthreads();
    float rinv = sh_rinv, sc = sh_sc;
    unsigned* qr = (unsigned*)(g_q + (size_t)row * D_DIM);
#pragma unroll
    for (int i = 0; i < 4; i++) {
        float a[4] = { v[i].x, v[i].y, v[i].z, v[i].w };
        unsigned pk = 0;
#pragma unroll
        for (int j = 0; j < 4; j++) {
            float xn = a[j] * rinv;
            float r = rintf(xn * sc);                // round half-to-even == jnp.round
            r = fminf(fmaxf(r, -128.f), 127.f);
            pk |= ((unsigned)((int)r & 0xff)) << (j * 8);
        }
        qr[tid + i * 256] = pk;
    }
}

// ============================================================================
// Kernel 4: int8 IMMA GEMM.  out[m,n] = (sum_d q[m,d]*w[n,d]) * g_rs[m]
// CTA 128x128, 8 warps (2m x 4n), warp tile 64x32, K pipeline 3-stage cp.async.
// ============================================================================
__global__ void __launch_bounds__(256, 2) gemm_kernel(float* __restrict__ out) {
    extern __shared__ char smem[];
    const uint32_t sbase = smem_to_u32(smem);
    const int tid = threadIdx.x;
    const int wid = tid >> 5, lane = tid & 31;
    const int warp_m = wid >> 2;          // 0..1
    const int warp_n = wid & 3;           // 0..3
    const int m0 = blockIdx.y * TILE_M;
    const int n0 = blockIdx.x * TILE_N;

    const int8_t* gA = g_q + (size_t)m0 * D_DIM;
    const int8_t* gB = g_w + (size_t)n0 * D_DIM;

    // per-thread load coords: 2 units of 16B each for A and B per chunk
    const int u0 = tid * 2, u1 = tid * 2 + 1;
    const int ar0 = u0 >> 2, ac0 = u0 & 3;
    const int ar1 = u1 >> 2, ac1 = u1 & 3;

    auto issue_chunk = [&](int kc, int stage) {
        uint32_t sa = sbase + stage * STAGE_SZ + A_OFF;
        uint32_t sb = sbase + stage * STAGE_SZ + B_OFF;
        const int8_t* pa = gA + (size_t)kc * TILE_K;
        const int8_t* pb = gB + (size_t)kc * TILE_K;
        cp_async16(sa + sw_off(ar0, ac0), pa + (size_t)ar0 * D_DIM + ac0 * 16);
        cp_async16(sa + sw_off(ar1, ac1), pa + (size_t)ar1 * D_DIM + ac1 * 16);
        cp_async16(sb + sw_off(ar0, ac0), pb + (size_t)ar0 * D_DIM + ac0 * 16);
        cp_async16(sb + sw_off(ar1, ac1), pb + (size_t)ar1 * D_DIM + ac1 * 16);
        cp_commit();
    };

    int acc[4][4][4];
#pragma unroll
    for (int i = 0; i < 4; i++)
#pragma unroll
        for (int j = 0; j < 4; j++)
#pragma unroll
            for (int c = 0; c < 4; c++) acc[i][j][c] = 0;

    // ldmatrix lane coords (shared by A and B fragment loads)
    const int lr = (lane & 7) + ((lane >> 3) & 1) * 8;   // row within 16-row frag
    const int lk = lane >> 4;                             // which k16 half

    issue_chunk(0, 0);
    issue_chunk(1, 1);

    for (int kc = 0; kc < KCHUNKS; kc++) {
        if (kc + 2 < KCHUNKS) issue_chunk(kc + 2, (kc + 2) % NSTAGE);
        cp_wait<2>();
        __syncthreads();

        const uint32_t sa = sbase + (kc % NSTAGE) * STAGE_SZ + A_OFF;
        const uint32_t sb = sbase + (kc % NSTAGE) * STAGE_SZ + B_OFF;

#pragma unroll
        for (int ks = 0; ks < 2; ks++) {              // two k32 steps per chunk
            const int k16b = 2 * ks + lk;
            uint32_t afr[4][4];
#pragma unroll
            for (int mf = 0; mf < 4; mf++)
                ldm_x4(afr[mf], sa + sw_off(warp_m * 64 + mf * 16 + lr, k16b));
            uint32_t bfr[2][4];
#pragma unroll
            for (int h = 0; h < 2; h++)
                ldm_x4(bfr[h], sb + sw_off(warp_n * 32 + h * 16 + lr, k16b));
#pragma unroll
            for (int mf = 0; mf < 4; mf++) {
#pragma unroll
                for (int nf = 0; nf < 4; nf++) {
                    uint32_t b0 = bfr[nf >> 1][nf & 1];
                    uint32_t b1 = bfr[nf >> 1][(nf & 1) + 2];
                    mma_s8(acc[mf][nf], afr[mf], b0, b1);
                }
            }
        }
        __syncthreads();
    }

    // Epilogue: out = acc * (1/x_scale^2)
    const int group = lane >> 2, tig = lane & 3;
#pragma unroll
    for (int mf = 0; mf < 4; mf++) {
        int r0 = m0 + warp_m * 64 + mf * 16 + group;
        float rs0 = g_rs[r0];
        float rs1 = g_rs[r0 + 8];
        float* o0 = out + (size_t)r0 * D_DIM;
        float* o1 = out + (size_t)(r0 + 8) * D_DIM;
#pragma unroll
        for (int nf = 0; nf < 4; nf++) {
            int col = n0 + warp_n * 32 + nf * 8 + tig * 2;
            float2 v0, v1;
            v0.x = (float)acc[mf][nf][0] * rs0;
            v0.y = (float)acc[mf][nf][1] * rs0;
            v1.x = (float)acc[mf][nf][2] * rs1;
            v1.y = (float)acc[mf][nf][3] * rs1;
            *(float2*)(o0 + col) = v0;
            *(float2*)(o1 + col) = v1;
        }
    }
}

// ============================================================================
// kernel_launch
// ============================================================================
extern "C" void kernel_launch(void* const* d_in, const int* in_sizes, int n_in,
                              void* d_out, int out_size) {
    const float* x    = (const float*)d_in[0];
    const float* kern = (const float*)d_in[1];
    if (n_in >= 2 && in_sizes[0] < in_sizes[1]) {    // x is the bigger tensor
        x    = (const float*)d_in[1];
        kern = (const float*)d_in[0];
    }

    cudaFuncSetAttribute(gemm_kernel, cudaFuncAttributeMaxDynamicSharedMemorySize, SMEM_BYTES);

    zero_kernel<<<1, 1>>>();
    ksum_kernel<<<1024, 256>>>(kern);
    sign_kernel<<<dim3(D_DIM / 32, D_DIM / 32), dim3(32, 32)>>>(kern);
    quant_kernel<<<M_ROWS, 256>>>(x);
    // n-tiles fastest: 32 consecutive CTAs share one A panel; all of g_w is L2-resident
    gemm_kernel<<<dim3(D_DIM / TILE_N, M_ROWS / TILE_M), 256, SMEM_BYTES>>>((float*)d_out);
}